// round 12
// baseline (speedup 1.0000x reference)
#include <cuda_runtime.h>

typedef unsigned long long u64;

#define SEQ    1024
#define BATCH  512
#define NT     64
#define CH     4
#define NCHUNK (SEQ / CH)   /* 256 */
#define WPB    4            /* warps (=batches) per block */
#define NBLK   (BATCH / WPB)

__device__ float    g_num[BATCH];
__device__ float    g_den[BATCH];
__device__ unsigned g_cnt;   /* zero-initialized; self-resets each launch */

// ---- packed f32x2 helpers ----
__device__ __forceinline__ u64 fma2(u64 a, u64 b, u64 c) {
    u64 d; asm("fma.rn.f32x2 %0, %1, %2, %3;" : "=l"(d) : "l"(a), "l"(b), "l"(c));
    return d;
}
__device__ __forceinline__ u64 add2(u64 a, u64 b) {
    u64 d; asm("add.rn.f32x2 %0, %1, %2;" : "=l"(d) : "l"(a), "l"(b));
    return d;
}
__device__ __forceinline__ float2 unpack2(u64 a) {
    float2 r; asm("mov.b64 {%0,%1}, %2;" : "=f"(r.x), "=f"(r.y) : "l"(a));
    return r;
}
__device__ __forceinline__ u64 pack2(float x, float y) {
    u64 d; asm("mov.b64 %0, {%1,%2};" : "=l"(d) : "f"(x), "f"(y));
    return d;
}

// ---------------------------------------------------------------------------
// Fused kernel: one WARP per batch. Lane j owns columns j and j+32.
// Alpha interleaved in smem (slot 2j = col j, slot 2j+1 = col j+32).
// Alpha exchange is warp-internal: one STS.64 (all lanes) followed by
// LDS.128 reads of the SAME warp — ordered through the per-warp LSU queue,
// so no __syncwarp is needed (volatile asm prevents compiler reordering).
// Emissions staged per-lane in registers (CH=4 chunk lead). Fused gold-path
// numerator + last-block reduction.
// ---------------------------------------------------------------------------
__global__ __launch_bounds__(128, 1) void fused_kernel(
    const float* __restrict__ em,
    const void* __restrict__ tags_raw,
    const int* __restrict__ mask,
    const float* __restrict__ startT,
    const float* __restrict__ endT,
    const float* __restrict__ trans,
    float* __restrict__ out)
{
    const int w = threadIdx.x >> 5;   // warp in block: 0..3
    const int j = threadIdx.x & 31;   // lane
    const int b = blockIdx.x * WPB + w;

    // ---- tags dtype detect (jax x64 -> int64, default -> int32) ----
    const int*       tags32 = (const int*)tags_raw;
    const long long* tags64 = (const long long*)tags_raw;
    unsigned nz = __ballot_sync(0xffffffffu, tags32[2 * j + 1] != 0);
    const int is64 = (nz == 0);

    // ---- E pairs matching interleaved alpha slots (pair i = rows i, i+32) --
    u64 EPa[32], EPb[32];
    #pragma unroll
    for (int i = 0; i < 32; i++) {
        EPa[i] = pack2(__expf(trans[i * NT + j]),
                       __expf(trans[(i + 32) * NT + j]));
        EPb[i] = pack2(__expf(trans[i * NT + j + 32]),
                       __expf(trans[(i + 32) * NT + j + 32]));
    }

    __shared__ __align__(16) float a_s[WPB][2][NT];
    __shared__ short stags[WPB][SEQ];
    __shared__ __align__(8) char smask[WPB][SEQ];

    // ---- preload tags + mask columns ----
    int mcnt = 0;
    #pragma unroll
    for (int t0 = 0; t0 < SEQ; t0 += 32) {
        int t  = t0 + j;
        int mv = mask[t * BATCH + b];
        smask[w][t] = (char)mv;
        mcnt += mv;
        size_t idx = (size_t)t * BATCH + b;
        stags[w][t] = (short)(is64 ? (int)tags64[idx] : tags32[idx]);
    }
    __syncwarp();   // once: tags/mask visible for cross-lane reads below

    // smem addresses for the two alpha buffers
    const unsigned abase = (unsigned)__cvta_generic_to_shared(&a_s[w][0][0]);

    // ---- stage chunk 0 emissions into registers ----
    float eca[CH], ecb[CH];
    #pragma unroll
    for (int c = 0; c < CH; c++) {
        size_t base = ((size_t)c * BATCH + b) * NT;
        eca[c] = em[base + j];
        ecb[c] = em[base + j + 32];
    }
    #pragma unroll
    for (int c = 0; c < CH; c++) {
        eca[c] = __expf(eca[c]);
        ecb[c] = __expf(ecb[c]);
    }

    // alpha0 (interleaved write: one STS.64)
    float a_pa = __expf(startT[j])      * eca[0];
    float a_pb = __expf(startT[j + 32]) * ecb[0];
    asm volatile("st.shared.v2.f32 [%0], {%1, %2};"
                 :: "r"(abase + j * 8), "f"(a_pa), "f"(a_pb) : "memory");

    float logacc = 0.f;
    float rs     = 1.0f;
    int   p      = 0;

    // numerator pipeline state (slice t = k*32 + j, valid for k < 32)
    float score = 0.f;
    float tv_p = 0.f, ev_p = 0.f;
    int   pm_p = 0;

    for (int k = 0; k < NCHUNK; k++) {
        // issue emission loads for chunk k+1 (register destination)
        float lda[CH], ldb[CH];
        if (k + 1 < NCHUNK) {
            const size_t base = ((size_t)(k + 1) * CH * BATCH + b) * NT;
            #pragma unroll
            for (int c = 0; c < CH; c++) {
                size_t o = base + (size_t)c * BATCH * NT;
                lda[c] = em[o + j];
                ldb[c] = em[o + j + 32];
            }
        }

        // mask bytes for this chunk: one LDS.32
        const unsigned mword = *(const unsigned*)&smask[w][k * CH];

        // numerator: consume last chunk's gathers, issue this chunk's
        if (k >= 1 && k <= 32)
            score += pm_p ? (tv_p + ev_p) : 0.f;
        if (k < 32) {
            int t   = k * 32 + j;
            int cur = stags[w][t];
            if (t == 0) {
                tv_p = startT[cur];
                ev_p = em[(size_t)b * NT + cur];
                pm_p = 1;
            } else {
                pm_p = smask[w][t];
                tv_p = trans[stags[w][t - 1] * NT + cur];
                ev_p = em[((size_t)t * BATCH + b) * NT + cur];
            }
        }

        const int c0 = (k == 0) ? 1 : 0;
        #pragma unroll
        for (int c = 0; c < CH; c++) {
            if (c < c0) continue;

            const unsigned rd = abase + (unsigned)p * (NT * 4);
            const unsigned wr = abase + (unsigned)(p ^ 1) * (NT * 4);

            const int mc = (int)((mword >> (8 * c)) & 0xffu);

            u64 aA[4] = {0ull, 0ull, 0ull, 0ull};
            u64 aB[4] = {0ull, 0ull, 0ull, 0ull};
            #pragma unroll
            for (int q = 0; q < 16; q++) {          // 16 x LDS.128 broadcast
                u64 vx, vy;
                asm volatile("ld.shared.v2.u64 {%0, %1}, [%2];"
                             : "=l"(vx), "=l"(vy) : "r"(rd + q * 16));
                const int r = 2 * q;
                aA[r & 3]       = fma2(vx, EPa[r],     aA[r & 3]);
                aA[(r + 1) & 3] = fma2(vy, EPa[r + 1], aA[(r + 1) & 3]);
                aB[r & 3]       = fma2(vx, EPb[r],     aB[r & 3]);
                aB[(r + 1) & 3] = fma2(vy, EPb[r + 1], aB[(r + 1) & 3]);
            }
            float2 fA = unpack2(add2(add2(aA[0], aA[1]), add2(aA[2], aA[3])));
            float2 fB = unpack2(add2(add2(aB[0], aB[1]), add2(aB[2], aB[3])));
            float dotA = fA.x + fA.y;
            float dotB = fB.x + fB.y;

            float v_a = mc ? dotA * (eca[c] * rs) : a_pa * rs;
            float v_b = mc ? dotB * (ecb[c] * rs) : a_pb * rs;

            // one STS.64; later LDS of this warp are ordered behind it in
            // the LSU queue — no syncwarp needed (single convergent warp)
            asm volatile("st.shared.v2.f32 [%0], {%1, %2};"
                         :: "r"(wr + j * 8), "f"(v_a), "f"(v_b) : "memory");
            a_pa = v_a;
            a_pb = v_b;
            p ^= 1;

            if (((k * CH + c) & 7) == 0) {   // t % 8 == 0: renorm by alpha[0]
                float az;
                asm volatile("ld.shared.f32 %0, [%1];" : "=f"(az) : "r"(wr));
                rs = __fdividef(1.0f, az);   // consumed next step
                logacc += __logf(az);
            } else {
                rs = 1.0f;
            }
        }

        // exp the staged loads for chunk k+1 (registers; no sync needed)
        if (k + 1 < NCHUNK) {
            #pragma unroll
            for (int c = 0; c < CH; c++) {
                eca[c] = __expf(lda[c]);
                ecb[c] = __expf(ldb[c]);
            }
        }
    }

    // ---- denominator epilogue (warp-local) ----
    float s = a_pa * __expf(endT[j]) + a_pb * __expf(endT[j + 32]);
    #pragma unroll
    for (int o = 16; o; o >>= 1)
        s += __shfl_xor_sync(0xffffffffu, s, o);
    if (j == 0)
        g_den[b] = logacc + __logf(s);

    // ---- numerator epilogue (warp-local) ----
    #pragma unroll
    for (int o = 16; o; o >>= 1) {
        score += __shfl_down_sync(0xffffffffu, score, o);
        mcnt  += __shfl_down_sync(0xffffffffu, mcnt, o);
    }
    if (j == 0)
        g_num[b] = score + endT[stags[w][mcnt - 1]];

    // ---- last-block final reduction (deterministic: fixed sum order) ----
    __threadfence();
    __syncthreads();
    __shared__ int is_last;
    if (threadIdx.x == 0) {
        unsigned prev = atomicAdd(&g_cnt, 1u);
        is_last = (prev == NBLK - 1);
    }
    __syncthreads();
    if (is_last) {
        __threadfence();
        int tid = threadIdx.x;  // 0..127
        float v = 0.f;
        #pragma unroll
        for (int r = 0; r < BATCH / 128; r++) {
            int i = tid + r * 128;
            v += g_num[i] - g_den[i];
        }
        #pragma unroll
        for (int o = 16; o; o >>= 1)
            v += __shfl_down_sync(0xffffffffu, v, o);
        __shared__ float ws[4];
        if ((tid & 31) == 0) ws[tid >> 5] = v;
        __syncthreads();
        if (tid == 0) {
            out[0] = (ws[0] + ws[1]) + (ws[2] + ws[3]);
            g_cnt = 0;   // reset for next graph replay
        }
    }
}

// ---------------------------------------------------------------------------
// inputs (metadata order): emissions f32, tags i64-or-i32, mask i32,
//                          start_transitions f32, end_transitions f32,
//                          transitions f32.  output: f32 scalar.
// ---------------------------------------------------------------------------
extern "C" void kernel_launch(void* const* d_in, const int* in_sizes, int n_in,
                              void* d_out, int out_size)
{
    const float* em     = (const float*)d_in[0];
    const void*  tags   = d_in[1];
    const int*   mask   = (const int*)d_in[2];
    const float* startT = (const float*)d_in[3];
    const float* endT   = (const float*)d_in[4];
    const float* trans  = (const float*)d_in[5];
    float*       out    = (float*)d_out;

    fused_kernel<<<NBLK, 32 * WPB>>>(em, tags, mask, startT, endT, trans, out);
}

// round 13
// speedup vs baseline: 1.2375x; 1.2375x over previous
#include <cuda_runtime.h>
#include <cuda_bf16.h>

typedef unsigned long long u64;

#define SEQ    1024
#define BATCH  512
#define NT     64
#define CH     8
#define NCHUNK (SEQ / CH)   /* 128 */
#define WPB    4            /* warps (=batches) per block */
#define NBLK   (BATCH / WPB)

__device__ float    g_num[BATCH];
__device__ float    g_den[BATCH];
__device__ unsigned g_cnt;   /* zero-initialized; self-resets each launch */

__device__ __forceinline__ __nv_bfloat162 u2b(unsigned u) {
    union { unsigned u; __nv_bfloat162 b; } c; c.u = u; return c.b;
}

// ---------------------------------------------------------------------------
// Fused kernel: one WARP per batch. Lane j owns columns j and j+32.
// Alpha stored as bf16x2 in smem: slot i = (alpha_row_i, alpha_row_{i+32});
// lane j writes slot j = (its col j value, its col j+32 value). Dot product
// in bf16 HFMA2 (rt 2, 1 MAC/cyc — beats f32x2's banking-limited rt 3).
// E pairs prepacked bf16x2 in registers (64 regs). Emissions staged per-lane
// raw in registers, expf per step. Renorm every 8 steps by alpha slot 0's
// low half. Fused gold-path numerator + last-block final reduction.
// ---------------------------------------------------------------------------
__global__ __launch_bounds__(128, 1) void fused_kernel(
    const float* __restrict__ em,
    const void* __restrict__ tags_raw,
    const int* __restrict__ mask,
    const float* __restrict__ startT,
    const float* __restrict__ endT,
    const float* __restrict__ trans,
    float* __restrict__ out)
{
    const int w = threadIdx.x >> 5;   // warp in block: 0..3
    const int j = threadIdx.x & 31;   // lane
    const int b = blockIdx.x * WPB + w;

    // ---- tags dtype detect (jax x64 -> int64, default -> int32) ----
    const int*       tags32 = (const int*)tags_raw;
    const long long* tags64 = (const long long*)tags_raw;
    unsigned nz = __ballot_sync(0xffffffffu, tags32[2 * j + 1] != 0);
    const int is64 = (nz == 0);

    // ---- E pairs bf16x2: EPa[i] = (expT[i][j], expT[i+32][j]) ----
    __nv_bfloat162 EPa[32], EPb[32];
    #pragma unroll
    for (int i = 0; i < 32; i++) {
        EPa[i] = __floats2bfloat162_rn(__expf(trans[i * NT + j]),
                                       __expf(trans[(i + 32) * NT + j]));
        EPb[i] = __floats2bfloat162_rn(__expf(trans[i * NT + j + 32]),
                                       __expf(trans[(i + 32) * NT + j + 32]));
    }

    __shared__ __align__(16) __nv_bfloat162 a_s[WPB][2][32];
    __shared__ short stags[WPB][SEQ];
    __shared__ __align__(8) char smask[WPB][SEQ];

    // ---- preload tags + mask columns ----
    int mcnt = 0;
    #pragma unroll
    for (int t0 = 0; t0 < SEQ; t0 += 32) {
        int t  = t0 + j;
        int mv = mask[t * BATCH + b];
        smask[w][t] = (char)mv;
        mcnt += mv;
        size_t idx = (size_t)t * BATCH + b;
        stags[w][t] = (short)(is64 ? (int)tags64[idx] : tags32[idx]);
    }

    // ---- stage chunk 0 raw emissions into registers ----
    float era[CH], erb[CH];
    #pragma unroll
    for (int c = 0; c < CH; c++) {
        size_t base = ((size_t)c * BATCH + b) * NT;
        era[c] = em[base + j];
        erb[c] = em[base + j + 32];
    }

    // alpha0
    float a_pa = __expf(startT[j] + era[0]);
    float a_pb = __expf(startT[j + 32] + erb[0]);
    a_s[w][0][j] = __floats2bfloat162_rn(a_pa, a_pb);
    __syncwarp();

    float logacc = 0.f;
    float rs     = 1.0f;
    int   p      = 0;

    // numerator pipeline state (slice t = k*32 + j, valid for k < 32)
    float score = 0.f;
    float tv_p = 0.f, ev_p = 0.f;
    int   pm_p = 0;

    for (int k = 0; k < NCHUNK; k++) {
        // issue raw emission loads for chunk k+1
        float lda[CH], ldb[CH];
        if (k + 1 < NCHUNK) {
            const size_t base = ((size_t)(k + 1) * CH * BATCH + b) * NT;
            #pragma unroll
            for (int c = 0; c < CH; c++) {
                size_t o = base + (size_t)c * BATCH * NT;
                lda[c] = em[o + j];
                ldb[c] = em[o + j + 32];
            }
        }

        // mask bytes for this chunk: one LDS.64
        const u64 mword = *(const u64*)&smask[w][k * CH];

        // numerator: consume last chunk's gathers, issue this chunk's
        if (k >= 1 && k <= 32)
            score += pm_p ? (tv_p + ev_p) : 0.f;
        if (k < 32) {
            int t   = k * 32 + j;
            int cur = stags[w][t];
            if (t == 0) {
                tv_p = startT[cur];
                ev_p = em[(size_t)b * NT + cur];
                pm_p = 1;
            } else {
                pm_p = smask[w][t];
                tv_p = trans[stags[w][t - 1] * NT + cur];
                ev_p = em[((size_t)t * BATCH + b) * NT + cur];
            }
        }

        const int c0 = (k == 0) ? 1 : 0;
        #pragma unroll
        for (int c = 0; c < CH; c++) {
            if (c < c0) continue;

            const int mc = (int)((mword >> (8 * c)) & 0xff);

            // per-step emission exp (2 MUFU, interleaves with HFMA2 stream)
            float ea = __expf(era[c]);
            float eb = __expf(erb[c]);

            const uint4* ap = (const uint4*)&a_s[w][p][0];
            __nv_bfloat162 z = __floats2bfloat162_rn(0.f, 0.f);
            __nv_bfloat162 aA[8] = {z, z, z, z, z, z, z, z};
            __nv_bfloat162 aB[8] = {z, z, z, z, z, z, z, z};
            #pragma unroll
            for (int q = 0; q < 8; q++) {       // 8 x LDS.128 broadcast
                uint4 v = ap[q];
                const int s = 4 * q;
                __nv_bfloat162 b0 = u2b(v.x), b1 = u2b(v.y),
                               b2 = u2b(v.z), b3 = u2b(v.w);
                aA[(s + 0) & 7] = __hfma2(b0, EPa[s + 0], aA[(s + 0) & 7]);
                aA[(s + 1) & 7] = __hfma2(b1, EPa[s + 1], aA[(s + 1) & 7]);
                aA[(s + 2) & 7] = __hfma2(b2, EPa[s + 2], aA[(s + 2) & 7]);
                aA[(s + 3) & 7] = __hfma2(b3, EPa[s + 3], aA[(s + 3) & 7]);
                aB[(s + 0) & 7] = __hfma2(b0, EPb[s + 0], aB[(s + 0) & 7]);
                aB[(s + 1) & 7] = __hfma2(b1, EPb[s + 1], aB[(s + 1) & 7]);
                aB[(s + 2) & 7] = __hfma2(b2, EPb[s + 2], aB[(s + 2) & 7]);
                aB[(s + 3) & 7] = __hfma2(b3, EPb[s + 3], aB[(s + 3) & 7]);
            }
            __nv_bfloat162 sA =
                __hadd2(__hadd2(__hadd2(aA[0], aA[1]), __hadd2(aA[2], aA[3])),
                        __hadd2(__hadd2(aA[4], aA[5]), __hadd2(aA[6], aA[7])));
            __nv_bfloat162 sB =
                __hadd2(__hadd2(__hadd2(aB[0], aB[1]), __hadd2(aB[2], aB[3])),
                        __hadd2(__hadd2(aB[4], aB[5]), __hadd2(aB[6], aB[7])));
            float dotA = __low2float(sA) + __high2float(sA);
            float dotB = __low2float(sB) + __high2float(sB);

            float v_a = mc ? dotA * (ea * rs) : a_pa * rs;
            float v_b = mc ? dotB * (eb * rs) : a_pb * rs;

            a_s[w][p ^ 1][j] = __floats2bfloat162_rn(v_a, v_b);
            a_pa = v_a;
            a_pb = v_b;
            __syncwarp();
            p ^= 1;

            if (c == 0) {   // t % 8 == 0 renorm by alpha slot 0 low half
                float az = __low2float(a_s[w][p][0]);
                rs = __fdividef(1.0f, az);   // consumed next step
                logacc += __logf(az);
            } else {
                rs = 1.0f;
            }
        }

        // roll staged emissions
        if (k + 1 < NCHUNK) {
            #pragma unroll
            for (int c = 0; c < CH; c++) {
                era[c] = lda[c];
                erb[c] = ldb[c];
            }
        }
    }

    // ---- denominator epilogue (warp-local; fp32 shadows) ----
    float s = a_pa * __expf(endT[j]) + a_pb * __expf(endT[j + 32]);
    #pragma unroll
    for (int o = 16; o; o >>= 1)
        s += __shfl_xor_sync(0xffffffffu, s, o);
    if (j == 0)
        g_den[b] = logacc + __logf(s);

    // ---- numerator epilogue (warp-local) ----
    #pragma unroll
    for (int o = 16; o; o >>= 1) {
        score += __shfl_down_sync(0xffffffffu, score, o);
        mcnt  += __shfl_down_sync(0xffffffffu, mcnt, o);
    }
    if (j == 0)
        g_num[b] = score + endT[stags[w][mcnt - 1]];

    // ---- last-block final reduction (deterministic: fixed sum order) ----
    __threadfence();
    __syncthreads();
    __shared__ int is_last;
    if (threadIdx.x == 0) {
        unsigned prev = atomicAdd(&g_cnt, 1u);
        is_last = (prev == NBLK - 1);
    }
    __syncthreads();
    if (is_last) {
        __threadfence();
        int tid = threadIdx.x;  // 0..127
        float v = 0.f;
        #pragma unroll
        for (int r = 0; r < BATCH / 128; r++) {
            int i = tid + r * 128;
            v += g_num[i] - g_den[i];
        }
        #pragma unroll
        for (int o = 16; o; o >>= 1)
            v += __shfl_down_sync(0xffffffffu, v, o);
        __shared__ float ws[4];
        if ((tid & 31) == 0) ws[tid >> 5] = v;
        __syncthreads();
        if (tid == 0) {
            out[0] = (ws[0] + ws[1]) + (ws[2] + ws[3]);
            g_cnt = 0;   // reset for next graph replay
        }
    }
}

// ---------------------------------------------------------------------------
// inputs (metadata order): emissions f32, tags i64-or-i32, mask i32,
//                          start_transitions f32, end_transitions f32,
//                          transitions f32.  output: f32 scalar.
// ---------------------------------------------------------------------------
extern "C" void kernel_launch(void* const* d_in, const int* in_sizes, int n_in,
                              void* d_out, int out_size)
{
    const float* em     = (const float*)d_in[0];
    const void*  tags   = d_in[1];
    const int*   mask   = (const int*)d_in[2];
    const float* startT = (const float*)d_in[3];
    const float* endT   = (const float*)d_in[4];
    const float* trans  = (const float*)d_in[5];
    float*       out    = (float*)d_out;

    fused_kernel<<<NBLK, 32 * WPB>>>(em, tags, mask, startT, endT, trans, out);
}